// round 14
// baseline (speedup 1.0000x reference)
#include <cuda_runtime.h>
#include <math.h>

#define BB 8
#define LL 8192
#define DD 768
#define NE 128
#define NPAIR (NE*(NE-1)/2)   // 8128
#define NP4   (DD/4)          // 192
#define KSPLIT 16
#define KC     (DD/KSPLIT)    // 48
#define KC4    (KC/4)         // 12
#define PITCH  132
#define NTILE  136
#define TPB    512

#define SSTR   772                     // padded floats per staged span (bank shift)
#define GBUF   (16*SSTR)               // floats per span-group buffer
#define NBUF   3
#define SMEM_DYN ((KC*PITCH + NBUF*GBUF) * 4)   // 25344 + 148224 = 173568 B

typedef unsigned long long ull;

// quarter pair ranges (triu row-major): rows [32q,32q+32)
__device__ __constant__ int c_qoff[5] = {0, 3568, 6112, 7632, 8128};

// Scratch (no allocations allowed)
__device__ float  g_par[KSPLIT][BB*NE*NE]; // raw gram partials (upper tiles)
__device__ double g_qs[BB][4][2];          // per-quarter fp64 {sum,sumsq}
__device__ float  g_cinv[BB];              // 1/(std+1e-5)
// counters: all return to 0 every launch (replay-safe)
__device__ int g_simcnt[BB];  // syrk arrivals (16)
__device__ int g_sobs[BB];    // stats observers of simcnt (4) -> resets both
__device__ int g_scnt[BB];    // stats qs arrivals (4) -> last computes cinv
__device__ int g_ready[BB];   // cinv ready (1)
__device__ int g_rcnt[BB];    // ready consumers (4) -> resets ready,rcnt

// ---- acq/rel primitives ---------------------------------------------------
__device__ __forceinline__ void red_add_release(int* p, int v) {
    asm volatile("red.release.gpu.global.add.s32 [%0], %1;"
                 :: "l"(p), "r"(v) : "memory");
}
__device__ __forceinline__ int atom_add_acqrel(int* p, int v) {
    int r;
    asm volatile("atom.acq_rel.gpu.global.add.s32 %0, [%1], %2;"
                 : "=r"(r) : "l"(p), "r"(v) : "memory");
    return r;
}
__device__ __forceinline__ int ld_acquire(const int* p) {
    int r;
    asm volatile("ld.acquire.gpu.global.s32 %0, [%1];"
                 : "=r"(r) : "l"(p) : "memory");
    return r;
}
__device__ __forceinline__ void st_release(int* p, int v) {
    asm volatile("st.release.gpu.global.s32 [%0], %1;"
                 :: "l"(p), "r"(v) : "memory");
}

// ---- cp.async helpers ------------------------------------------------------
__device__ __forceinline__ void cp16(unsigned dst, const void* src, int pred) {
    asm volatile("{\n\t.reg .pred q;\n\tsetp.ne.u32 q, %2, 0;\n\t"
                 "@q cp.async.cg.shared.global [%0], [%1], 16;\n\t}"
                 :: "r"(dst), "l"(src), "r"(pred) : "memory");
}
__device__ __forceinline__ void cp_commit() {
    asm volatile("cp.async.commit_group;" ::: "memory");
}
template<int N> __device__ __forceinline__ void cp_wait() {
    asm volatile("cp.async.wait_group %0;" :: "n"(N) : "memory");
}

// ---- packed f32x2 helpers ------------------------------------------------
__device__ __forceinline__ void fma2(ull &d, ull a, ull b) {
    asm("fma.rn.f32x2 %0, %1, %2, %0;" : "+l"(d) : "l"(a), "l"(b));
}
__device__ __forceinline__ ull pack2(float v) {
    ull r; unsigned u = __float_as_uint(v);
    asm("mov.b64 %0, {%1, %1};" : "=l"(r) : "r"(u));
    return r;
}
__device__ __forceinline__ void unpack2(ull v, float &lo, float &hi) {
    unsigned a, b;
    asm("mov.b64 {%0, %1}, %2;" : "=r"(a), "=r"(b) : "l"(v));
    lo = __uint_as_float(a); hi = __uint_as_float(b);
}

// ---------------------------------------------------------------------------
__global__ void __launch_bounds__(TPB, 1)
k_all(const float* __restrict__ x,
      const int*   __restrict__ starts,
      const int*   __restrict__ lengths,
      const int*   __restrict__ hts,
      const float* __restrict__ thr,
      const float* __restrict__ W1,
      const float* __restrict__ b1,
      const float* __restrict__ W2,
      const float* __restrict__ b2,
      float*       __restrict__ out) {
    const int blk = blockIdx.x;           // 0..127
    const int b   = blk >> 4;             // batch
    const int kc  = blk & 15;             // k-chunk
    const int tid = threadIdx.x;          // 512

    extern __shared__ __align__(16) float dyn[];
    float (*At)[PITCH] = reinterpret_cast<float (*)[PITCH]>(dyn);   // 48x132
    float* stage = dyn + KC*PITCH;        // NBUF x 16 spans x SSTR
    float* sSim  = dyn;                   // reused (32x128) after syrk

    __shared__ int    sSt[NE], sLn[NE];
    __shared__ float  sRi[NE];
    __shared__ float  r0[128], r1[128], r2[128], r3[128];
    __shared__ int    rf[128];
    __shared__ double sS16[16], sQ16[16];

    // ======= Phase A: cp.async pipelined gather-pool =======================
    if (tid < NE) {
        sSt[tid] = starts[b*NE + tid];
        sLn[tid] = lengths[b*NE + tid];
    }
    __syncthreads();

    const int w    = tid >> 5;            // warp = span within group
    const int lane = tid & 31;
    const unsigned stage_u32 = (unsigned)__cvta_generic_to_shared(stage);

    // issue one group's cp.asyncs (warp w -> span g*16+w)
    auto issue_group = [&](int g, int bufi) {
        if (lane < 24) {
            const int sp = g*16 + w;
            const int c  = lane % 12;      // f4 slot
            const int tp = lane / 12;      // row parity
            const int len = sLn[sp];
            const float4* src = (const float4*)x
                + ((long)b*LL + sSt[sp])*NP4 + kc*KC4 + c;
            const unsigned dst0 = stage_u32 + (unsigned)(bufi*GBUF + w*SSTR + c*4)*4u;
            #pragma unroll
            for (int tb = 0; tb < 16; tb += 2) {
                const int t = tb + tp;
                cp16(dst0 + (unsigned)t*48u*4u, src + (long)t*NP4, t < len);
            }
        }
    };
    // reduce one landed group into At
    auto reduce_group = [&](int g, int bufi) {
        if (lane < 12) {
            const int sp  = g*16 + w;
            const int len = sLn[sp];       // warp-uniform
            const float4* row = (const float4*)(stage + bufi*GBUF + w*SSTR) + lane;
            float4 a = make_float4(0.f, 0.f, 0.f, 0.f);
            for (int t = 0; t < len; ++t) {
                const float4 v = row[t*12];
                a.x += v.x; a.y += v.y; a.z += v.z; a.w += v.w;
            }
            const float il = 1.0f / (float)len;
            At[4*lane+0][sp] = a.x*il;
            At[4*lane+1][sp] = a.y*il;
            At[4*lane+2][sp] = a.z*il;
            At[4*lane+3][sp] = a.w*il;
        }
    };

    issue_group(0, 0); cp_commit();
    issue_group(1, 1); cp_commit();
    issue_group(2, 2); cp_commit();
    #pragma unroll 1
    for (int g = 0; g < 8; ++g) {
        if (g <= 5)      cp_wait<2>();
        else if (g == 6) cp_wait<1>();
        else             cp_wait<0>();
        __syncthreads();                   // all warps' group g landed
        reduce_group(g, g % NBUF);
        __syncthreads();                   // buffer free before reuse
        if (g + 3 < 8) { issue_group(g + 3, (g + 3) % NBUF); cp_commit(); }
    }
    __syncthreads();

    // ======= Phase B: upper-triangular FFMA2 syrk (8x8 tiles) ==============
    if (tid < NTILE) {
        const int tp = 135 - tid;
        const int m  = (int)((sqrtf((float)(8*tp + 1)) - 1.0f) * 0.5f);
        const int ty = 15 - m;
        const int tx = 15 - (tp - (m*(m+1)) / 2);
        const int i8 = ty*8, j8 = tx*8;

        ull c[8][4];
        #pragma unroll
        for (int r = 0; r < 8; ++r)
            #pragma unroll
            for (int q = 0; q < 4; ++q) c[r][q] = 0ull;

        #pragma unroll 4
        for (int kk = 0; kk < KC; ++kk) {
            const float4 alo = *(const float4*)&At[kk][i8];
            const float4 ahi = *(const float4*)&At[kk][i8 + 4];
            ull a2[8];
            a2[0]=pack2(alo.x); a2[1]=pack2(alo.y); a2[2]=pack2(alo.z); a2[3]=pack2(alo.w);
            a2[4]=pack2(ahi.x); a2[5]=pack2(ahi.y); a2[6]=pack2(ahi.z); a2[7]=pack2(ahi.w);
            const ulonglong2 bv0 = *(const ulonglong2*)&At[kk][j8];
            const ulonglong2 bv1 = *(const ulonglong2*)&At[kk][j8 + 4];
            ull bb[4] = {bv0.x, bv0.y, bv1.x, bv1.y};
            #pragma unroll
            for (int r = 0; r < 8; ++r)
                #pragma unroll
                for (int q = 0; q < 4; ++q) fma2(c[r][q], a2[r], bb[q]);
        }

        float* P = g_par[kc] + (long)b*NE*NE + i8*NE + j8;
        #pragma unroll
        for (int r = 0; r < 8; ++r) {
            float l0,h0,l1,h1,l2,h2,l3,h3;
            unpack2(c[r][0], l0, h0);
            unpack2(c[r][1], l1, h1);
            unpack2(c[r][2], l2, h2);
            unpack2(c[r][3], l3, h3);
            __stcg(&((float4*)(P + (long)r*NE))[0], make_float4(l0, h0, l1, h1));
            __stcg(&((float4*)(P + (long)r*NE))[1], make_float4(l2, h2, l3, h3));
        }
    }
    __syncthreads();
    if (tid == 0) red_add_release(&g_simcnt[b], 1);

    if (kc >= 4) return;                  // non-stats blocks done

    // ======= Phase C (kc<4): MLP collapse while others finish ==============
    const int q = kc;
    if (tid < 128) {
        const float w1  = W1[tid];
        const float w20 = W2[2*tid], w21 = W2[2*tid+1];
        r0[tid] = (w1 > 0.f) ? w1*w20 : 0.f;
        r1[tid] = (w1 > 0.f) ? w1*w21 : 0.f;
        r2[tid] = (w1 < 0.f) ? w1*w20 : 0.f;
        r3[tid] = (w1 < 0.f) ? w1*w21 : 0.f;
        rf[tid] = (b1[tid] != 0.f) ? 1 : 0;
    }
    __syncthreads();
    #pragma unroll
    for (int o = 64; o > 0; o >>= 1) {
        if (tid < o) {
            r0[tid]+=r0[tid+o]; r1[tid]+=r1[tid+o];
            r2[tid]+=r2[tid+o]; r3[tid]+=r3[tid+o];
            rf[tid]|=rf[tid+o];
        }
        __syncthreads();
    }

    // ---- wait for all 16 syrk chunk blocks of this batch ----
    if (tid == 0) {
        while (ld_acquire(&g_simcnt[b]) < KSPLIT) __nanosleep(32);
        const int a = atom_add_acqrel(&g_sobs[b], 1);
        if (a == 3) { g_sobs[b] = 0; g_simcnt[b] = 0; }   // last observer resets
    }
    __syncthreads();

    // ---- ALL 128 diagonal norms locally ----
    if (tid < NE) {
        const float* D = g_par[0] + (long)b*NE*NE + (long)tid*(NE+1);
        float d = 0.f;
        #pragma unroll
        for (int k2 = 0; k2 < KSPLIT; ++k2)
            d += __ldcg(D + (long)k2*(BB*NE*NE));
        sRi[tid] = rsqrtf(fmaxf(d, 1e-16f));
    }

    // ---- sum 16 partial planes for this quarter (2 f4/thread) ----
    float4 acc[2];
    #pragma unroll
    for (int it = 0; it < 2; ++it) {
        const int f = q*1024 + tid + it*512;
        float4 a = make_float4(0.f,0.f,0.f,0.f);
        #pragma unroll
        for (int k2 = 0; k2 < KSPLIT; ++k2) {
            const float4 v = __ldcg(&((const float4*)(g_par[k2] + (long)b*NE*NE))[f]);
            a.x+=v.x; a.y+=v.y; a.z+=v.z; a.w+=v.w;
        }
        acc[it] = a;
    }
    __syncthreads();                      // sRi ready; dyn reuse safe

    // ---- normalize, write sim to smem, weighted stats ----
    float s = 0.f, qq = 0.f;
    #pragma unroll
    for (int it = 0; it < 2; ++it) {
        const int f  = q*1024 + tid + it*512;
        const int i  = f >> 5;
        const int j0 = (f & 31) * 4;
        const float ri = sRi[i];
        float4 v = acc[it];
        v.x *= ri * sRi[j0  ];
        v.y *= ri * sRi[j0+1];
        v.z *= ri * sRi[j0+2];
        v.w *= ri * sRi[j0+3];
        ((float4*)sSim)[(i - q*32)*32 + (f & 31)] = v;
        const float wx = (j0   > i) ? 2.f : (j0   == i) ? 1.f : 0.f;
        const float wy = (j0+1 > i) ? 2.f : (j0+1 == i) ? 1.f : 0.f;
        const float wz = (j0+2 > i) ? 2.f : (j0+2 == i) ? 1.f : 0.f;
        const float ww = (j0+3 > i) ? 2.f : (j0+3 == i) ? 1.f : 0.f;
        s  += wx*v.x + wy*v.y + wz*v.z + ww*v.w;
        qq += wx*v.x*v.x + wy*v.y*v.y + wz*v.z*v.z + ww*v.w*v.w;
    }
    double ds = (double)s, dq = (double)qq;
    #pragma unroll
    for (int o = 16; o > 0; o >>= 1) {
        ds += __shfl_xor_sync(0xffffffffu, ds, o);
        dq += __shfl_xor_sync(0xffffffffu, dq, o);
    }
    if ((tid & 31) == 0) { sS16[tid >> 5] = ds; sQ16[tid >> 5] = dq; }
    __syncthreads();
    if (tid == 0) {
        double ts = 0.0, tq = 0.0;
        #pragma unroll
        for (int w2 = 0; w2 < 16; ++w2) { ts += sS16[w2]; tq += sQ16[w2]; }
        g_qs[b][q][0] = ts;
        g_qs[b][q][1] = tq;
        const int a3 = atom_add_acqrel(&g_scnt[b], 1);
        if (a3 == 3) {                    // deterministic fixed-order combine
            double fs = 0.0, fq = 0.0;
            #pragma unroll
            for (int q2 = 0; q2 < 4; ++q2) { fs += g_qs[b][q2][0]; fq += g_qs[b][q2][1]; }
            const double n  = (double)(NE*NE);
            const double sd = sqrt((fq - fs*fs/n) / (n - 1.0));
            g_cinv[b] = 1.0f / ((float)sd + 1e-5f);
            g_scnt[b] = 0;
            st_release(&g_ready[b], 1);
        }
        while (ld_acquire(&g_ready[b]) == 0) __nanosleep(32);
        const int a4 = atom_add_acqrel(&g_rcnt[b], 1);
        if (a4 == 3) { g_rcnt[b] = 0; g_ready[b] = 0; }
    }
    __syncthreads();

    // ======= Phase E: classify this quarter's contiguous pair range ========
    {
        const float cinv = __ldcg(&g_cinv[b]);
        const float t0   = __ldg(thr);
        const float b20  = __ldg(&b2[0]), b21 = __ldg(&b2[1]);
        const int p0 = c_qoff[q], p1 = c_qoff[q+1];

        for (int p = p0 + tid; p < p1; p += TPB) {
            const int gp = b*NPAIR + p;
            const int2 ht = ((const int2*)hts)[gp];
            float sim;
            if ((ht.x >> 5) == q) {
                sim = sSim[(ht.x - q*32)*NE + ht.y];
            } else {
                // defensive fallback: bit-identical recompute from partials
                const long off = (long)b*NE*NE + ht.x*NE + ht.y;
                float raw = 0.f;
                #pragma unroll
                for (int k2 = 0; k2 < KSPLIT; ++k2) raw += __ldcg(&g_par[k2][off]);
                sim = raw * sRi[ht.x] * sRi[ht.y];
            }
            const float pv = (sim - t0) * cinv;
            float o0, o1;
            if (rf[0] == 0) {
                o0 = fmaf(pv, (pv > 0.f) ? r0[0] : r2[0], b20);
                o1 = fmaf(pv, (pv > 0.f) ? r1[0] : r3[0], b21);
            } else {
                o0 = b20; o1 = b21;
                for (int k = 0; k < 128; ++k) {
                    const float h = fmaxf(fmaf(pv, __ldg(&W1[k]), __ldg(&b1[k])), 0.f);
                    o0 = fmaf(h, __ldg(&W2[2*k  ]), o0);
                    o1 = fmaf(h, __ldg(&W2[2*k+1]), o1);
                }
            }
            ((float2*)out)[gp] = make_float2(o0, o1);
        }
    }
}

// ---------------------------------------------------------------------------
extern "C" void kernel_launch(void* const* d_in, const int* in_sizes, int n_in,
                              void* d_out, int out_size) {
    const float* x       = (const float*)d_in[0];
    const int*   starts  = (const int*)  d_in[1];
    const int*   lengths = (const int*)  d_in[2];
    const int*   hts     = (const int*)  d_in[3];
    const float* thr     = (const float*)d_in[4];
    const float* W1      = (const float*)d_in[5];
    const float* b1      = (const float*)d_in[6];
    const float* W2      = (const float*)d_in[7];
    const float* b2      = (const float*)d_in[8];
    float* out = (float*)d_out;

    cudaFuncSetAttribute(k_all, cudaFuncAttributeMaxDynamicSharedMemorySize, SMEM_DYN);
    k_all<<<BB*KSPLIT, TPB, SMEM_DYN>>>(x, starts, lengths, hts, thr,
                                        W1, b1, W2, b2, out);
}

// round 15
// speedup vs baseline: 1.4270x; 1.4270x over previous
#include <cuda_runtime.h>
#include <math.h>

#define BB 8
#define LL 8192
#define DD 768
#define NE 128
#define NPAIR (NE*(NE-1)/2)   // 8128 = 16*508
#define NP4   (DD/4)          // 192
#define KSPLIT 16
#define KC     (DD/KSPLIT)    // 48
#define KC4    (KC/4)         // 12
#define PITCH  132
#define NTILE  272            // 8x4 tiles, tx >= 2*ty  (16 x 32 tile grid)
#define TPB    512

typedef unsigned long long ull;

// Scratch (no allocations allowed)
__device__ float  g_par[KSPLIT][BB*NE*NE]; // raw gram partials (upper tiles; lower stays 0)
__device__ float  g_sim[BB*NE*NE];         // summed normalized sims
__device__ double g_qs[BB][KSPLIT][2];     // per-band fp64 {sum,sumsq}
__device__ float  g_cinv[BB];              // 1/(std+1e-5)
// counters: all return to 0 every launch (replay-safe)
__device__ int g_simcnt[BB];  // syrk arrivals (16)
__device__ int g_sobs[BB];    // observers of simcnt (16) -> resets both
__device__ int g_scnt[BB];    // band-stats arrivals (16) -> last computes cinv
__device__ int g_ready[BB];   // cinv+sim ready (1)
__device__ int g_rcnt[BB];    // ready consumers (16) -> resets ready,rcnt

// ---- acq/rel primitives ---------------------------------------------------
__device__ __forceinline__ void red_add_release(int* p, int v) {
    asm volatile("red.release.gpu.global.add.s32 [%0], %1;"
                 :: "l"(p), "r"(v) : "memory");
}
__device__ __forceinline__ int atom_add_acqrel(int* p, int v) {
    int r;
    asm volatile("atom.acq_rel.gpu.global.add.s32 %0, [%1], %2;"
                 : "=r"(r) : "l"(p), "r"(v) : "memory");
    return r;
}
__device__ __forceinline__ int ld_acquire(const int* p) {
    int r;
    asm volatile("ld.acquire.gpu.global.s32 %0, [%1];"
                 : "=r"(r) : "l"(p) : "memory");
    return r;
}
__device__ __forceinline__ void st_release(int* p, int v) {
    asm volatile("st.release.gpu.global.s32 [%0], %1;"
                 :: "l"(p), "r"(v) : "memory");
}

// ---- packed f32x2 helpers ------------------------------------------------
__device__ __forceinline__ void fma2(ull &d, ull a, ull b) {
    asm("fma.rn.f32x2 %0, %1, %2, %0;" : "+l"(d) : "l"(a), "l"(b));
}
__device__ __forceinline__ ull pack2(float v) {
    ull r; unsigned u = __float_as_uint(v);
    asm("mov.b64 %0, {%1, %1};" : "=l"(r) : "r"(u));
    return r;
}
__device__ __forceinline__ void unpack2(ull v, float &lo, float &hi) {
    unsigned a, b;
    asm("mov.b64 {%0, %1}, %2;" : "=r"(a), "=r"(b) : "l"(v));
    lo = __uint_as_float(a); hi = __uint_as_float(b);
}

// ---------------------------------------------------------------------------
__global__ void __launch_bounds__(TPB, 1)
k_all(const float* __restrict__ x,
      const int*   __restrict__ starts,
      const int*   __restrict__ lengths,
      const int*   __restrict__ hts,
      const float* __restrict__ thr,
      const float* __restrict__ W1,
      const float* __restrict__ b1,
      const float* __restrict__ W2,
      const float* __restrict__ b2,
      float*       __restrict__ out) {
    const int blk = blockIdx.x;           // 0..127
    const int b   = blk >> 4;             // batch
    const int kc  = blk & 15;             // k-chunk == band id == pair-chunk id
    const int tid = threadIdx.x;          // 512

    __shared__ __align__(16) float At[KC][PITCH];    // pooled k-slice [k][span]
    __shared__ int    sSt[NE], sLn[NE];
    __shared__ float  sRi[NE];
    __shared__ float  r0[128], r1[128], r2[128], r3[128];
    __shared__ int    rf[128];
    __shared__ double sS16[16], sQ16[16];

    // ======= Phase A: gather-pool 48-float slice, 4 concurrent spans =======
    if (tid < NE) {
        sSt[tid] = starts[b*NE + tid];
        sLn[tid] = lengths[b*NE + tid];
    }
    __syncthreads();
    {
        const int grp = tid >> 4;         // 0..31
        const int c   = tid & 15;         // f4 slot (0..11 active)
        if (c < 12) {
            const float4* xb4 = (const float4*)x + (long)b*LL*NP4 + kc*KC4 + c;
            const int sp0 = grp,      sp1 = grp + 32;
            const int sp2 = grp + 64, sp3 = grp + 96;
            const int l0 = sLn[sp0], l1 = sLn[sp1], l2 = sLn[sp2], l3 = sLn[sp3];
            const float4* p0 = xb4 + (long)sSt[sp0]*NP4;
            const float4* p1 = xb4 + (long)sSt[sp1]*NP4;
            const float4* p2 = xb4 + (long)sSt[sp2]*NP4;
            const float4* p3 = xb4 + (long)sSt[sp3]*NP4;

            float4 a0 = make_float4(0,0,0,0), a1 = a0, a2 = a0, a3 = a0;
            #pragma unroll
            for (int t = 0; t < 16; ++t) {
                if (t < l0) { const float4 v = __ldcs(p0 + (long)t*NP4); a0.x+=v.x; a0.y+=v.y; a0.z+=v.z; a0.w+=v.w; }
                if (t < l1) { const float4 v = __ldcs(p1 + (long)t*NP4); a1.x+=v.x; a1.y+=v.y; a1.z+=v.z; a1.w+=v.w; }
                if (t < l2) { const float4 v = __ldcs(p2 + (long)t*NP4); a2.x+=v.x; a2.y+=v.y; a2.z+=v.z; a2.w+=v.w; }
                if (t < l3) { const float4 v = __ldcs(p3 + (long)t*NP4); a3.x+=v.x; a3.y+=v.y; a3.z+=v.z; a3.w+=v.w; }
            }
            const float i0 = 1.0f/(float)l0, i1 = 1.0f/(float)l1;
            const float i2 = 1.0f/(float)l2, i3 = 1.0f/(float)l3;
            At[4*c+0][sp0] = a0.x*i0; At[4*c+1][sp0] = a0.y*i0;
            At[4*c+2][sp0] = a0.z*i0; At[4*c+3][sp0] = a0.w*i0;
            At[4*c+0][sp1] = a1.x*i1; At[4*c+1][sp1] = a1.y*i1;
            At[4*c+2][sp1] = a1.z*i1; At[4*c+3][sp1] = a1.w*i1;
            At[4*c+0][sp2] = a2.x*i2; At[4*c+1][sp2] = a2.y*i2;
            At[4*c+2][sp2] = a2.z*i2; At[4*c+3][sp2] = a2.w*i2;
            At[4*c+0][sp3] = a3.x*i3; At[4*c+1][sp3] = a3.y*i3;
            At[4*c+2][sp3] = a3.z*i3; At[4*c+3][sp3] = a3.w*i3;
        }
    }
    __syncthreads();

    // ======= Phase B: upper-triangular FFMA2 syrk (8x4 tiles, 272 thr) =====
    if (tid < NTILE) {
        int ty = 0, off = 0;              // tid -> (ty, tx), tx >= 2*ty
        #pragma unroll
        for (int y = 0; y < 15; ++y) {
            const int cnt = 32 - 2*ty;
            if (tid - off >= cnt) { off += cnt; ty++; }
        }
        const int tx = 2*ty + (tid - off);
        const int i8 = ty*8, j4 = tx*4;

        ull c[8][2];
        #pragma unroll
        for (int r = 0; r < 8; ++r) { c[r][0] = 0ull; c[r][1] = 0ull; }

        #pragma unroll 4
        for (int kk = 0; kk < KC; ++kk) {
            const float4 alo = *(const float4*)&At[kk][i8];
            const float4 ahi = *(const float4*)&At[kk][i8 + 4];
            ull a2[8];
            a2[0]=pack2(alo.x); a2[1]=pack2(alo.y); a2[2]=pack2(alo.z); a2[3]=pack2(alo.w);
            a2[4]=pack2(ahi.x); a2[5]=pack2(ahi.y); a2[6]=pack2(ahi.z); a2[7]=pack2(ahi.w);
            const ulonglong2 bv = *(const ulonglong2*)&At[kk][j4];
            #pragma unroll
            for (int r = 0; r < 8; ++r) {
                fma2(c[r][0], a2[r], bv.x);
                fma2(c[r][1], a2[r], bv.y);
            }
        }

        float* P = g_par[kc] + (long)b*NE*NE + i8*NE + j4;
        #pragma unroll
        for (int r = 0; r < 8; ++r) {
            float l0,h0,l1,h1;
            unpack2(c[r][0], l0, h0);
            unpack2(c[r][1], l1, h1);
            __stcg((float4*)(P + (long)r*NE), make_float4(l0, h0, l1, h1));
        }
    }
    __syncthreads();
    if (tid == 0) red_add_release(&g_simcnt[b], 1);

    // ======= Phase C: MLP collapse (input-only) while others finish ========
    if (tid < 128) {
        const float w1  = W1[tid];
        const float w20 = W2[2*tid], w21 = W2[2*tid+1];
        r0[tid] = (w1 > 0.f) ? w1*w20 : 0.f;
        r1[tid] = (w1 > 0.f) ? w1*w21 : 0.f;
        r2[tid] = (w1 < 0.f) ? w1*w20 : 0.f;
        r3[tid] = (w1 < 0.f) ? w1*w21 : 0.f;
        rf[tid] = (b1[tid] != 0.f) ? 1 : 0;
    }
    __syncthreads();
    #pragma unroll
    for (int o = 64; o > 0; o >>= 1) {
        if (tid < o) {
            r0[tid]+=r0[tid+o]; r1[tid]+=r1[tid+o];
            r2[tid]+=r2[tid+o]; r3[tid]+=r3[tid+o];
            rf[tid]|=rf[tid+o];
        }
        __syncthreads();
    }

    // ---- wait for all 16 syrk chunk blocks of this batch ----
    if (tid == 0) {
        while (ld_acquire(&g_simcnt[b]) < KSPLIT) __nanosleep(32);
        const int a = atom_add_acqrel(&g_sobs[b], 1);
        if (a == KSPLIT - 1) { g_sobs[b] = 0; g_simcnt[b] = 0; }  // last resets
    }
    __syncthreads();

    // ---- all 128 diagonal norms locally (L2 hits) ----
    if (tid < NE) {
        const float* D = g_par[0] + (long)b*NE*NE + (long)tid*(NE+1);
        float d = 0.f;
        #pragma unroll
        for (int k2 = 0; k2 < KSPLIT; ++k2)
            d += __ldcg(D + (long)k2*(BB*NE*NE));
        sRi[tid] = rsqrtf(fmaxf(d, 1e-16f));
    }
    __syncthreads();

    // ======= Phase D: band sum + normalize + stats (band = rows 8kc..8kc+7)
    float s = 0.f, qq = 0.f;
    if (tid < 256) {
        const int f  = kc*256 + tid;      // f4 index within batch plane
        const int i  = f >> 5;
        const int j0 = (f & 31) * 4;
        float4 a = make_float4(0.f,0.f,0.f,0.f);
        #pragma unroll
        for (int k2 = 0; k2 < KSPLIT; ++k2) {
            const float4 v = __ldcg(&((const float4*)(g_par[k2] + (long)b*NE*NE))[f]);
            a.x+=v.x; a.y+=v.y; a.z+=v.z; a.w+=v.w;
        }
        const float ri = sRi[i];
        a.x *= ri * sRi[j0  ];
        a.y *= ri * sRi[j0+1];
        a.z *= ri * sRi[j0+2];
        a.w *= ri * sRi[j0+3];
        __stcg(&((float4*)(g_sim + (long)b*NE*NE))[f], a);
        const float wx = (j0   > i) ? 2.f : (j0   == i) ? 1.f : 0.f;
        const float wy = (j0+1 > i) ? 2.f : (j0+1 == i) ? 1.f : 0.f;
        const float wz = (j0+2 > i) ? 2.f : (j0+2 == i) ? 1.f : 0.f;
        const float ww = (j0+3 > i) ? 2.f : (j0+3 == i) ? 1.f : 0.f;
        s  += wx*a.x + wy*a.y + wz*a.z + ww*a.w;
        qq += wx*a.x*a.x + wy*a.y*a.y + wz*a.z*a.z + ww*a.w*a.w;
    }
    double ds = (double)s, dq = (double)qq;
    #pragma unroll
    for (int o = 16; o > 0; o >>= 1) {
        ds += __shfl_xor_sync(0xffffffffu, ds, o);
        dq += __shfl_xor_sync(0xffffffffu, dq, o);
    }
    if ((tid & 31) == 0) { sS16[tid >> 5] = ds; sQ16[tid >> 5] = dq; }
    __syncthreads();
    if (tid == 0) {
        double ts = 0.0, tq = 0.0;
        #pragma unroll
        for (int w2 = 0; w2 < 16; ++w2) { ts += sS16[w2]; tq += sQ16[w2]; }
        g_qs[b][kc][0] = ts;
        g_qs[b][kc][1] = tq;
        const int a3 = atom_add_acqrel(&g_scnt[b], 1);
        if (a3 == KSPLIT - 1) {           // deterministic fixed-order combine
            double fs = 0.0, fq = 0.0;
            #pragma unroll
            for (int q2 = 0; q2 < KSPLIT; ++q2) { fs += g_qs[b][q2][0]; fq += g_qs[b][q2][1]; }
            const double n  = (double)(NE*NE);
            const double sd = sqrt((fq - fs*fs/n) / (n - 1.0));
            g_cinv[b] = 1.0f / ((float)sd + 1e-5f);
            g_scnt[b] = 0;
            st_release(&g_ready[b], 1);
        }
        while (ld_acquire(&g_ready[b]) == 0) __nanosleep(32);
        const int a4 = atom_add_acqrel(&g_rcnt[b], 1);
        if (a4 == KSPLIT - 1) { g_rcnt[b] = 0; g_ready[b] = 0; }
    }
    __syncthreads();

    // ======= Phase E: classify 508 pairs (chunk kc of batch b) =============
    {
        const float cinv = __ldcg(&g_cinv[b]);
        const float t0   = __ldg(thr);
        const float b20  = __ldg(&b2[0]), b21 = __ldg(&b2[1]);

        if (tid < 508) {
            const int gp = b*NPAIR + kc*508 + tid;
            const int2 ht = ((const int2*)hts)[gp];
            const float sim = __ldcg(&g_sim[(long)b*NE*NE + ht.x*NE + ht.y]);
            const float pv  = (sim - t0) * cinv;
            float o0, o1;
            if (rf[0] == 0) {
                o0 = fmaf(pv, (pv > 0.f) ? r0[0] : r2[0], b20);
                o1 = fmaf(pv, (pv > 0.f) ? r1[0] : r3[0], b21);
            } else {
                o0 = b20; o1 = b21;
                #pragma unroll 8
                for (int k = 0; k < 128; ++k) {
                    const float h = fmaxf(fmaf(pv, __ldg(&W1[k]), __ldg(&b1[k])), 0.f);
                    o0 = fmaf(h, __ldg(&W2[2*k  ]), o0);
                    o1 = fmaf(h, __ldg(&W2[2*k+1]), o1);
                }
            }
            ((float2*)out)[gp] = make_float2(o0, o1);
        }
    }
}

// ---------------------------------------------------------------------------
extern "C" void kernel_launch(void* const* d_in, const int* in_sizes, int n_in,
                              void* d_out, int out_size) {
    const float* x       = (const float*)d_in[0];
    const int*   starts  = (const int*)  d_in[1];
    const int*   lengths = (const int*)  d_in[2];
    const int*   hts     = (const int*)  d_in[3];
    const float* thr     = (const float*)d_in[4];
    const float* W1      = (const float*)d_in[5];
    const float* b1      = (const float*)d_in[6];
    const float* W2      = (const float*)d_in[7];
    const float* b2      = (const float*)d_in[8];
    float* out = (float*)d_out;

    k_all<<<BB*KSPLIT, TPB>>>(x, starts, lengths, hts, thr, W1, b1, W2, b2, out);
}